// round 2
// baseline (speedup 1.0000x reference)
#include <cuda_runtime.h>
#include <cuda_bf16.h>

// DotPredictor: out[e] = sigmoid(dot(h[src[e]], h[dst[e]])), D = 64.
// NOTE: reference uses jnp.int64 but JAX x64 is disabled -> indices are int32.
// 16 lanes per edge; each lane: one float4 from src row + one from dst row.
// h (12.8 MB) is L2-resident; kernel is L2-gather-throughput bound.

#define D 64
#define LANES_PER_EDGE 16

__global__ void __launch_bounds__(256) dotpred_kernel(
    const float* __restrict__ h,
    const int* __restrict__ src,
    const int* __restrict__ dst,
    float* __restrict__ out,
    int E)
{
    int gid  = blockIdx.x * blockDim.x + threadIdx.x;
    int edge = gid >> 4;          // 16 lanes per edge
    int lane = gid & 15;
    if (edge >= E) return;

    // Uniform within the 16-lane group -> broadcast load
    int s = src[edge];
    int d = dst[edge];

    const float4* __restrict__ hs =
        reinterpret_cast<const float4*>(h + (long long)s * D);
    const float4* __restrict__ hd =
        reinterpret_cast<const float4*>(h + (long long)d * D);

    float4 a = hs[lane];
    float4 b = hd[lane];

    float acc = a.x * b.x;
    acc = fmaf(a.y, b.y, acc);
    acc = fmaf(a.z, b.z, acc);
    acc = fmaf(a.w, b.w, acc);

    // Reduce across the 16-lane group (xor pattern stays within group)
    acc += __shfl_xor_sync(0xFFFFFFFFu, acc, 8);
    acc += __shfl_xor_sync(0xFFFFFFFFu, acc, 4);
    acc += __shfl_xor_sync(0xFFFFFFFFu, acc, 2);
    acc += __shfl_xor_sync(0xFFFFFFFFu, acc, 1);

    if (lane == 0) {
        // fast sigmoid; rel-err budget is 1e-3, __expf is ~1e-6 accurate here
        out[edge] = 1.0f / (1.0f + __expf(-acc));
    }
}

extern "C" void kernel_launch(void* const* d_in, const int* in_sizes, int n_in,
                              void* d_out, int out_size)
{
    const float* h   = (const float*)d_in[0];
    const int*   src = (const int*)d_in[1];
    const int*   dst = (const int*)d_in[2];
    float*       out = (float*)d_out;

    int E = in_sizes[1];  // number of edges

    long long total_threads = (long long)E * LANES_PER_EDGE;
    int threads = 256;
    int blocks  = (int)((total_threads + threads - 1) / threads);

    dotpred_kernel<<<blocks, threads>>>(h, src, dst, out, E);
}

// round 3
// speedup vs baseline: 1.6128x; 1.6128x over previous
#include <cuda_runtime.h>
#include <cuda_bf16.h>

// DotPredictor: out[e] = sigmoid(dot(h[src[e]], h[dst[e]])), D = 64 fp32.
// Indices are int32 (JAX x64 disabled).
// 8 lanes per edge; each lane loads 2 float4 from src row + 2 from dst row
// (MLP=4), 16 FMAs, 3-step shfl reduction. h (12.8 MB) is L2-resident.

#define D 64

__global__ void __launch_bounds__(256) dotpred_kernel(
    const float* __restrict__ h,
    const int* __restrict__ src,
    const int* __restrict__ dst,
    float* __restrict__ out,
    int E)
{
    int gid  = blockIdx.x * blockDim.x + threadIdx.x;
    int edge = gid >> 3;          // 8 lanes per edge
    int lane = gid & 7;
    if (edge >= E) return;

    // Uniform within the 8-lane group -> broadcast load (src[e..] contiguous)
    int s = src[edge];
    int d = dst[edge];

    const float4* __restrict__ hs =
        reinterpret_cast<const float4*>(h + (long long)s * D);
    const float4* __restrict__ hd =
        reinterpret_cast<const float4*>(h + (long long)d * D);

    // 4 independent 16B loads in flight (two full 128B lines per row per group)
    float4 a0 = hs[lane];
    float4 a1 = hs[lane + 8];
    float4 b0 = hd[lane];
    float4 b1 = hd[lane + 8];

    float acc = a0.x * b0.x;
    acc = fmaf(a0.y, b0.y, acc);
    acc = fmaf(a0.z, b0.z, acc);
    acc = fmaf(a0.w, b0.w, acc);
    acc = fmaf(a1.x, b1.x, acc);
    acc = fmaf(a1.y, b1.y, acc);
    acc = fmaf(a1.z, b1.z, acc);
    acc = fmaf(a1.w, b1.w, acc);

    // Reduce across the 8-lane group (xor pattern stays within group)
    acc += __shfl_xor_sync(0xFFFFFFFFu, acc, 4);
    acc += __shfl_xor_sync(0xFFFFFFFFu, acc, 2);
    acc += __shfl_xor_sync(0xFFFFFFFFu, acc, 1);

    if (lane == 0) {
        out[edge] = 1.0f / (1.0f + __expf(-acc));
    }
}

extern "C" void kernel_launch(void* const* d_in, const int* in_sizes, int n_in,
                              void* d_out, int out_size)
{
    const float* h   = (const float*)d_in[0];
    const int*   src = (const int*)d_in[1];
    const int*   dst = (const int*)d_in[2];
    float*       out = (float*)d_out;

    int E = in_sizes[1];  // number of edges

    long long total_threads = (long long)E * 8;
    int threads = 256;
    int blocks  = (int)((total_threads + threads - 1) / threads);

    dotpred_kernel<<<blocks, threads>>>(h, src, dst, out, E);
}